// round 1
// baseline (speedup 1.0000x reference)
#include <cuda_runtime.h>
#include <math.h>
#include <stdint.h>

#define BATCH   4
#define LQ      1024
#define TSEQ    2048            // 2*L
#define DMODEL  256
#define DTIME   16
#define DDIM    272
#define NLAYER  4
#define DINNER  544
#define DSTATE  16
#define DCONV   4
#define DTRANK  17
#define NDBL    (DTRANK + 2*DSTATE)   // 49
#define MROWS   (BATCH*TSEQ)          // 8192
#define NCHUNK  32
#define CHUNK   (TSEQ/NCHUNK)         // 64

// ---------------- scratch (static device globals; no allocation) ----------------
__device__ float g_h   [MROWS*DDIM];
__device__ float g_res [MROWS*DDIM];
__device__ float g_hn  [MROWS*DDIM];
__device__ float g_xz  [MROWS*2*DINNER];
__device__ float g_xconv[MROWS*DINNER];
__device__ float g_dbl [MROWS*NDBL];
__device__ float g_delta[MROWS*DINNER];
__device__ float g_yg  [MROWS*DINNER];
__device__ float g_hend[BATCH*NCHUNK*DINNER*DSTATE];
__device__ float g_P   [BATCH*NCHUNK*DINNER*DSTATE];
__device__ float g_Hin [BATCH*NCHUNK*DINNER*DSTATE];

__device__ __forceinline__ float ex2(float x) {
    float y; asm("ex2.approx.ftz.f32 %0, %1;" : "=f"(y) : "f"(x)); return y;
}

// ---------------- embedding + temporal pe + sequence concat ----------------
__global__ void __launch_bounds__(DDIM) embed_kernel(
    const int* __restrict__ type_seq, const float* __restrict__ time_seq,
    const float* __restrict__ temp_seq, const float* __restrict__ emb)
{
    int row = blockIdx.x;            // 0..8191 : b*TSEQ + t
    int d = threadIdx.x;             // 0..271
    int b = row / TSEQ, t = row % TSEQ;
    float v;
    if (t < LQ) {
        if (d < DMODEL) {
            v = tanhf(emb[(size_t)type_seq[b*LQ + t]*DMODEL + d]);
        } else {
            int j = d - DMODEL;
            int i = j >> 1;
            // div_i = exp(-(2i)*ln(10000)/16)
            float div = expf(-0.57564627324851142f * (float)(2*i));
            float arg = time_seq[b*LQ + t] * div;
            v = (j & 1) ? cosf(arg) : sinf(arg);
        }
    } else {
        v = (d < DMODEL) ? 0.f
                         : temp_seq[(size_t)(b*LQ + (t - LQ))*DTIME + (d - DMODEL)];
    }
    g_h[(size_t)row*DDIM + d] = v;
}

// ---------------- residual add + layernorm ----------------
__global__ void __launch_bounds__(128) addnorm_kernel(
    const float* __restrict__ gamma, const float* __restrict__ beta, int addflag)
{
    int row = blockIdx.x;
    int tid = threadIdx.x;
    float v[3];
    float s = 0.f, s2 = 0.f;
#pragma unroll
    for (int j = 0; j < 3; j++) {
        int d = tid + j*128;
        float x = 0.f;
        if (d < DDIM) {
            x = g_h[(size_t)row*DDIM + d];
            if (addflag) x += g_res[(size_t)row*DDIM + d];
        }
        v[j] = x; s += x; s2 += x*x;
    }
#pragma unroll
    for (int o = 16; o > 0; o >>= 1) {
        s  += __shfl_down_sync(0xffffffffu, s,  o);
        s2 += __shfl_down_sync(0xffffffffu, s2, o);
    }
    __shared__ float ss[4], ss2[4];
    if ((tid & 31) == 0) { ss[tid >> 5] = s; ss2[tid >> 5] = s2; }
    __syncthreads();
    if (tid == 0) {
        float a  = ss[0]+ss[1]+ss[2]+ss[3];
        float a2 = ss2[0]+ss2[1]+ss2[2]+ss2[3];
        float mean = a * (1.f/DDIM);
        float var  = a2 * (1.f/DDIM) - mean*mean;
        ss[0] = mean;
        ss2[0] = rsqrtf(var + 1e-5f);
    }
    __syncthreads();
    float mean = ss[0], rstd = ss2[0];
#pragma unroll
    for (int j = 0; j < 3; j++) {
        int d = tid + j*128;
        if (d < DDIM) {
            g_res[(size_t)row*DDIM + d] = v[j];
            g_hn[(size_t)row*DDIM + d] = (v[j]-mean)*rstd*gamma[d] + beta[d];
        }
    }
}

// ---------------- final add + layernorm -> output (first LQ timesteps) ----------------
__global__ void __launch_bounds__(128) final_kernel(
    const float* __restrict__ gamma, const float* __restrict__ beta,
    float* __restrict__ out)
{
    int rowo = blockIdx.x;           // 0..4095 : b*LQ + t
    int tid = threadIdx.x;
    int b = rowo / LQ, t = rowo % LQ;
    int m = b*TSEQ + t;
    float v[3];
    float s = 0.f, s2 = 0.f;
#pragma unroll
    for (int j = 0; j < 3; j++) {
        int d = tid + j*128;
        float x = 0.f;
        if (d < DDIM) x = g_h[(size_t)m*DDIM + d] + g_res[(size_t)m*DDIM + d];
        v[j] = x; s += x; s2 += x*x;
    }
#pragma unroll
    for (int o = 16; o > 0; o >>= 1) {
        s  += __shfl_down_sync(0xffffffffu, s,  o);
        s2 += __shfl_down_sync(0xffffffffu, s2, o);
    }
    __shared__ float ss[4], ss2[4];
    if ((tid & 31) == 0) { ss[tid >> 5] = s; ss2[tid >> 5] = s2; }
    __syncthreads();
    if (tid == 0) {
        float a  = ss[0]+ss[1]+ss[2]+ss[3];
        float a2 = ss2[0]+ss2[1]+ss2[2]+ss2[3];
        float mean = a * (1.f/DDIM);
        float var  = a2 * (1.f/DDIM) - mean*mean;
        ss[0] = mean;
        ss2[0] = rsqrtf(var + 1e-5f);
    }
    __syncthreads();
    float mean = ss[0], rstd = ss2[0];
#pragma unroll
    for (int j = 0; j < 3; j++) {
        int d = tid + j*128;
        if (d < DDIM)
            out[(size_t)rowo*DDIM + d] = (v[j]-mean)*rstd*gamma[d] + beta[d];
    }
}

// ---------------- generic TN GEMM: C[M,N] = A[M,K] @ W[N,K]^T ----------------
// BM=128, BN=64, BK=16, 256 threads, 8x4 per-thread tile. K must be mult of 16.
__global__ void __launch_bounds__(256) gemm_tn(
    const float* __restrict__ A, const float* __restrict__ W,
    float* __restrict__ C, int M, int N, int K)
{
    __shared__ float As[16][132];
    __shared__ float Ws[16][68];
    int tid = threadIdx.x;
    int mb = blockIdx.y * 128;
    int nb = blockIdx.x * 64;
    int lr = tid >> 2;               // 0..63
    int lk = (tid & 3) << 2;         // 0,4,8,12
    int ty = tid >> 4;               // 0..15
    int tx = tid & 15;               // 0..15

    float acc[8][4];
#pragma unroll
    for (int i = 0; i < 8; i++)
#pragma unroll
        for (int j = 0; j < 4; j++) acc[i][j] = 0.f;

    const float* Arow0 = A + (size_t)(mb + lr) * K + lk;
    const float* Arow1 = Arow0 + (size_t)64 * K;
    bool wvalid = (nb + lr) < N;
    const float* Wrow = W + (size_t)(nb + lr) * K + lk;

    int ktiles = K >> 4;
    for (int kt = 0; kt < ktiles; kt++) {
        float4 a0 = *(const float4*)(Arow0 + kt*16);
        float4 a1 = *(const float4*)(Arow1 + kt*16);
        float4 w0 = wvalid ? *(const float4*)(Wrow + kt*16)
                           : make_float4(0.f, 0.f, 0.f, 0.f);
        __syncthreads();
        As[lk+0][lr] = a0.x; As[lk+1][lr] = a0.y; As[lk+2][lr] = a0.z; As[lk+3][lr] = a0.w;
        As[lk+0][lr+64] = a1.x; As[lk+1][lr+64] = a1.y; As[lk+2][lr+64] = a1.z; As[lk+3][lr+64] = a1.w;
        Ws[lk+0][lr] = w0.x; Ws[lk+1][lr] = w0.y; Ws[lk+2][lr] = w0.z; Ws[lk+3][lr] = w0.w;
        __syncthreads();
#pragma unroll
        for (int kk = 0; kk < 16; kk++) {
            float ra[8], rw[4];
            *(float4*)&ra[0] = *(const float4*)&As[kk][ty*8];
            *(float4*)&ra[4] = *(const float4*)&As[kk][ty*8 + 4];
            *(float4*)&rw[0] = *(const float4*)&Ws[kk][tx*4];
#pragma unroll
            for (int i = 0; i < 8; i++)
#pragma unroll
                for (int j = 0; j < 4; j++)
                    acc[i][j] = fmaf(ra[i], rw[j], acc[i][j]);
        }
    }
#pragma unroll
    for (int i = 0; i < 8; i++) {
        int m = mb + ty*8 + i;
#pragma unroll
        for (int j = 0; j < 4; j++) {
            int n = nb + tx*4 + j;
            if (n < N) C[(size_t)m*N + n] = acc[i][j];
        }
    }
}

// ---------------- depthwise causal conv1d + bias + silu ----------------
__global__ void __launch_bounds__(DINNER) conv_kernel(
    const float* __restrict__ conv_w, const float* __restrict__ conv_b, int layer)
{
    int m = blockIdx.x;              // b*TSEQ + t
    int d = threadIdx.x;
    int b = m / TSEQ, t = m % TSEQ;
    const float* wp = conv_w + (size_t)(layer*DINNER + d)*DCONV;
    float s = conv_b[layer*DINNER + d];
#pragma unroll
    for (int k = 0; k < DCONV; k++) {
        int tt = t - (DCONV-1) + k;
        if (tt >= 0)
            s = fmaf(wp[k], g_xz[(size_t)(b*TSEQ + tt)*(2*DINNER) + d], s);
    }
    float sl = s / (1.f + __expf(-s));
    g_xconv[(size_t)m*DINNER + d] = sl;
}

// ---------------- delta = softplus(dt @ dt_w^T + dt_b), K=17 ----------------
__global__ void __launch_bounds__(DINNER) delta_kernel(
    const float* __restrict__ dt_w, const float* __restrict__ dt_b, int layer)
{
    __shared__ float sdbl[16][DTRANK];
    int m0 = blockIdx.x * 16;
    int tid = threadIdx.x;
    if (tid < 16*DTRANK) {
        int mm = tid / DTRANK, r = tid % DTRANK;
        sdbl[mm][r] = g_dbl[(size_t)(m0+mm)*NDBL + r];
    }
    __syncthreads();
    int d = tid;
    float wreg[DTRANK];
#pragma unroll
    for (int r = 0; r < DTRANK; r++)
        wreg[r] = dt_w[(size_t)(layer*DINNER + d)*DTRANK + r];
    float bias = dt_b[layer*DINNER + d];
    for (int mm = 0; mm < 16; mm++) {
        float s = bias;
#pragma unroll
        for (int r = 0; r < DTRANK; r++) s = fmaf(sdbl[mm][r], wreg[r], s);
        float sp = fmaxf(s, 0.f) + log1pf(__expf(-fabsf(s)));
        g_delta[(size_t)(m0+mm)*DINNER + d] = sp;
    }
}

// ---------------- chunked selective scan ----------------
// Pass 1: local scan from h=0 per chunk; write end state + chunk decay P
__global__ void __launch_bounds__(DINNER) scan1_kernel(
    const float* __restrict__ A_log, int layer)
{
    int c = blockIdx.x, b = blockIdx.y;
    int d = threadIdx.x;
    const float LOG2E = 1.4426950408889634f;
    float A2[DSTATE];
#pragma unroll
    for (int n = 0; n < DSTATE; n++)
        A2[n] = -__expf(A_log[(size_t)(layer*DINNER + d)*DSTATE + n]) * LOG2E;
    float base = A2[0];
    bool fast = true;
#pragma unroll
    for (int n = 1; n < DSTATE; n++)
        fast = fast && (fabsf(A2[n] - (float)(n+1)*base)
                        <= 1e-4f*fabsf((float)(n+1)*base) + 1e-6f);

    float h[DSTATE];
#pragma unroll
    for (int n = 0; n < DSTATE; n++) h[n] = 0.f;
    float sumd = 0.f;
    __shared__ float sB[2][DSTATE];

    int m0 = b*TSEQ + c*CHUNK;
    for (int i = 0; i < CHUNK; i++) {
        int m = m0 + i;
        if (d < DSTATE) sB[i & 1][d] = g_dbl[(size_t)m*NDBL + DTRANK + d];
        float delta = g_delta[(size_t)m*DINNER + d];
        float u     = g_xconv[(size_t)m*DINNER + d];
        __syncthreads();
        float du = delta * u;
        if (fast) {
            float e1 = ex2(delta * base);
            float p = e1;
#pragma unroll
            for (int n = 0; n < DSTATE; n++) {
                h[n] = fmaf(p, h[n], du * sB[i & 1][n]);
                p *= e1;
            }
        } else {
#pragma unroll
            for (int n = 0; n < DSTATE; n++) {
                float a = ex2(delta * A2[n]);
                h[n] = fmaf(a, h[n], du * sB[i & 1][n]);
            }
        }
        sumd += delta;
    }
    size_t o = ((size_t)(b*NCHUNK + c)*DINNER + d)*DSTATE;
#pragma unroll
    for (int n = 0; n < DSTATE; n++) {
        g_hend[o + n] = h[n];
        g_P[o + n] = ex2(A2[n] * sumd);
    }
}

// Pass 2: sequential combine over 32 chunks per (b,d) lane
__global__ void scan2_kernel()
{
    int idx = blockIdx.x*blockDim.x + threadIdx.x;
    if (idx >= BATCH*DINNER) return;
    int b = idx / DINNER, d = idx % DINNER;
    float H[DSTATE];
#pragma unroll
    for (int n = 0; n < DSTATE; n++) H[n] = 0.f;
    for (int c = 0; c < NCHUNK; c++) {
        size_t o = ((size_t)(b*NCHUNK + c)*DINNER + d)*DSTATE;
#pragma unroll
        for (int n = 0; n < DSTATE; n++) g_Hin[o + n] = H[n];
#pragma unroll
        for (int n = 0; n < DSTATE; n++) H[n] = fmaf(g_P[o + n], H[n], g_hend[o + n]);
    }
}

// Pass 3: full scan with correct entry state; fused y = (scan + u*D)*silu(z)
__global__ void __launch_bounds__(DINNER) scan3_kernel(
    const float* __restrict__ A_log, const float* __restrict__ D_param, int layer)
{
    int c = blockIdx.x, b = blockIdx.y;
    int d = threadIdx.x;
    const float LOG2E = 1.4426950408889634f;
    float A2[DSTATE];
#pragma unroll
    for (int n = 0; n < DSTATE; n++)
        A2[n] = -__expf(A_log[(size_t)(layer*DINNER + d)*DSTATE + n]) * LOG2E;
    float base = A2[0];
    bool fast = true;
#pragma unroll
    for (int n = 1; n < DSTATE; n++)
        fast = fast && (fabsf(A2[n] - (float)(n+1)*base)
                        <= 1e-4f*fabsf((float)(n+1)*base) + 1e-6f);

    float h[DSTATE];
    size_t oin = ((size_t)(b*NCHUNK + c)*DINNER + d)*DSTATE;
#pragma unroll
    for (int n = 0; n < DSTATE; n++) h[n] = g_Hin[oin + n];
    float Dp = D_param[layer*DINNER + d];

    __shared__ float sBC[2][2*DSTATE];
    int m0 = b*TSEQ + c*CHUNK;
    for (int i = 0; i < CHUNK; i++) {
        int m = m0 + i;
        if (d < 2*DSTATE) sBC[i & 1][d] = g_dbl[(size_t)m*NDBL + DTRANK + d];
        float delta = g_delta[(size_t)m*DINNER + d];
        float u     = g_xconv[(size_t)m*DINNER + d];
        float z     = g_xz[(size_t)m*(2*DINNER) + DINNER + d];
        __syncthreads();
        float du = delta * u;
        float y = 0.f;
        if (fast) {
            float e1 = ex2(delta * base);
            float p = e1;
#pragma unroll
            for (int n = 0; n < DSTATE; n++) {
                h[n] = fmaf(p, h[n], du * sBC[i & 1][n]);
                y = fmaf(h[n], sBC[i & 1][DSTATE + n], y);
                p *= e1;
            }
        } else {
#pragma unroll
            for (int n = 0; n < DSTATE; n++) {
                float a = ex2(delta * A2[n]);
                h[n] = fmaf(a, h[n], du * sBC[i & 1][n]);
                y = fmaf(h[n], sBC[i & 1][DSTATE + n], y);
            }
        }
        float silz = z / (1.f + __expf(-z));
        g_yg[(size_t)m*DINNER + d] = fmaf(u, Dp, y) * silz;
    }
}

// ---------------- host launcher ----------------
extern "C" void kernel_launch(void* const* d_in, const int* in_sizes, int n_in,
                              void* d_out, int out_size)
{
    (void)in_sizes; (void)n_in; (void)out_size;
    const int*   type_seq = (const int*)  d_in[0];
    const float* time_seq = (const float*)d_in[1];
    const float* temp_seq = (const float*)d_in[2];
    const float* emb      = (const float*)d_in[3];
    const float* norm_w   = (const float*)d_in[4];
    const float* norm_b   = (const float*)d_in[5];
    const float* in_w     = (const float*)d_in[6];
    const float* conv_w   = (const float*)d_in[7];
    const float* conv_b   = (const float*)d_in[8];
    const float* xproj_w  = (const float*)d_in[9];
    const float* dt_w     = (const float*)d_in[10];
    const float* dt_b     = (const float*)d_in[11];
    const float* A_log    = (const float*)d_in[12];
    const float* D_param  = (const float*)d_in[13];
    const float* out_w    = (const float*)d_in[14];
    const float* normf_w  = (const float*)d_in[15];
    const float* normf_b  = (const float*)d_in[16];
    float* out = (float*)d_out;

    float *p_hn, *p_xz, *p_xconv, *p_dbl, *p_yg, *p_h;
    cudaGetSymbolAddress((void**)&p_hn,    g_hn);
    cudaGetSymbolAddress((void**)&p_xz,    g_xz);
    cudaGetSymbolAddress((void**)&p_xconv, g_xconv);
    cudaGetSymbolAddress((void**)&p_dbl,   g_dbl);
    cudaGetSymbolAddress((void**)&p_yg,    g_yg);
    cudaGetSymbolAddress((void**)&p_h,     g_h);

    embed_kernel<<<MROWS, DDIM>>>(type_seq, time_seq, temp_seq, emb);

    for (int l = 0; l < NLAYER; l++) {
        addnorm_kernel<<<MROWS, 128>>>(norm_w + l*DDIM, norm_b + l*DDIM, l > 0);

        // xz = hn @ in_w^T : (8192,272)x(1088,272)^T
        gemm_tn<<<dim3((2*DINNER + 63)/64, MROWS/128), 256>>>(
            p_hn, in_w + (size_t)l*2*DINNER*DDIM, p_xz, MROWS, 2*DINNER, DDIM);

        conv_kernel<<<MROWS, DINNER>>>(conv_w, conv_b, l);

        // dbl = xconv @ xproj_w^T : (8192,544)x(49,544)^T
        gemm_tn<<<dim3((NDBL + 63)/64, MROWS/128), 256>>>(
            p_xconv, xproj_w + (size_t)l*NDBL*DINNER, p_dbl, MROWS, NDBL, DINNER);

        delta_kernel<<<MROWS/16, DINNER>>>(dt_w, dt_b, l);

        scan1_kernel<<<dim3(NCHUNK, BATCH), DINNER>>>(A_log, l);
        scan2_kernel<<<(BATCH*DINNER + 255)/256, 256>>>();
        scan3_kernel<<<dim3(NCHUNK, BATCH), DINNER>>>(A_log, D_param, l);

        // h = yg @ out_w^T : (8192,544)x(272,544)^T
        gemm_tn<<<dim3((DDIM + 63)/64, MROWS/128), 256>>>(
            p_yg, out_w + (size_t)l*DDIM*DINNER, p_h, MROWS, DDIM, DINNER);
    }

    final_kernel<<<BATCH*LQ, 128>>>(normf_w, normf_b, out);
}